// round 3
// baseline (speedup 1.0000x reference)
#include <cuda_runtime.h>
#include <cstdint>

#define BB 32
#define NN 8500
#define GG 128
#define CC 80
#define TPB2 256

// ---------------- scratch (__device__ globals: no allocation allowed) ----------------
__device__ float         g_neg_sum[BB * NN];     // sum_c -log1p(-p)
__device__ float         g_bg_vfl [BB * NN];     // sum_c -log1p(-p)*0.75*p^2
__device__ unsigned char g_valid  [BB * NN];     // prior valid flag
__device__ unsigned int  g_match  [BB * NN * 4]; // 128-bit match mask per prior
__device__ double        g_acc[5];               // vfl, giou, dfl, npos, nscore

__device__ __forceinline__ float clampp(float p) {
    return fminf(fmaxf(p, 1e-7f), 1.0f - 1e-7f);
}

// monotone float -> uint32 (total order matching float <)
__device__ __forceinline__ unsigned f2mono(float f) {
    unsigned u = __float_as_uint(f);
    return (u & 0x80000000u) ? ~u : (u | 0x80000000u);
}

__device__ __forceinline__ float pair_iou(float4 d, float g0, float g1, float g2, float g3) {
    float tlx = fmaxf(d.x, g0), tly = fmaxf(d.y, g1);
    float brx = fminf(d.z, g2), bry = fminf(d.w, g3);
    float wx = fmaxf(brx - tlx, 0.f), wy = fmaxf(bry - tly, 0.f);
    float inter = wx * wy;
    float aa  = (d.z - d.x) * (d.w - d.y);
    float ab2 = (g2 - g0) * (g3 - g1);
    return inter / (aa + ab2 - inter + 1e-16f);
}

// cost composed exactly like the reference: (neg_sum - neg[lbl] + pos[lbl]) + 3*(-log(iou+1e-8))
__device__ __forceinline__ float pair_cost(float ns, float p, float iou) {
    // -neg[lbl] = log1p(-p); pos[lbl] = -log(p)
    float cls = ns + log1pf(-p) - logf(p);
    return cls + 3.f * (-logf(iou + 1e-8f));
}

// ---------------- kernel 1: per-prior prep (warp per prior) ----------------
__global__ void __launch_bounds__(256) k1_prep(
    const float4* __restrict__ priors,
    const float*  __restrict__ clsp,
    const float4* __restrict__ gtb)
{
    if (blockIdx.x == 0 && threadIdx.x < 5) g_acc[threadIdx.x] = 0.0;

    int w    = (blockIdx.x * blockDim.x + threadIdx.x) >> 5; // global warp = prior slot
    int lane = threadIdx.x & 31;
    if (w >= BB * NN) return;
    int b = w / NN, i = w - b * NN;

    const float* cp = clsp + (size_t)w * CC;
    float ns = 0.f, bg = 0.f;
    for (int c = lane; c < CC; c += 32) {
        float p   = clampp(cp[c]);
        float l1p = log1pf(-p);
        ns -= l1p;
        bg -= l1p * 0.75f * p * p;
    }
#pragma unroll
    for (int off = 16; off; off >>= 1) {
        ns += __shfl_down_sync(0xffffffffu, ns, off);
        bg += __shfl_down_sync(0xffffffffu, bg, off);
    }

    float4 pr = priors[i];
    float cx = pr.x, cy = pr.y, s = pr.z;
    const float4* gb = gtb + (size_t)b * GG;
    bool any = false;
#pragma unroll
    for (int g = lane; g < GG; g += 32) {
        float4 gq = gb[g];
        float ibv = fminf(fminf(cx - gq.x, cy - gq.y), fminf(gq.z - cx, gq.w - cy));
        float gcx = (gq.x + gq.z) * 0.5f, gcy = (gq.y + gq.w) * 0.5f;
        float r = 2.5f * s;
        float icv = fminf(fminf(cx - gcx + r, cy - gcy + r), fminf(gcx + r - cx, gcy + r - cy));
        any = any || (ibv > 0.f) || (icv > 0.f);
    }
    unsigned bal = __ballot_sync(0xffffffffu, any);
    if (lane == 0) {
        g_neg_sum[w] = ns;
        g_bg_vfl[w]  = bg;
        g_valid[w]   = bal ? 1 : 0;
    }
    if (lane < 4) g_match[(size_t)w * 4 + lane] = 0u;
}

// ---------------- kernel 2: SimOTA assignment, one block per (b,g) column ----------------
__global__ void __launch_bounds__(TPB2) k2_assign(
    const float4* __restrict__ priors,
    const float4* __restrict__ dec,
    const float*  __restrict__ clsp,
    const float4* __restrict__ gtb,
    const int*    __restrict__ gtl)
{
    const int g = blockIdx.x, b = blockIdx.y;
    const int tid = threadIdx.x;

    float4 gq = gtb[(size_t)b * GG + g];
    const float g0 = gq.x, g1 = gq.y, g2 = gq.z, g3 = gq.w;
    const float gcx = (g0 + g2) * 0.5f, gcy = (g1 + g3) * 0.5f;
    const int   lbl = gtl[b * GG + g];
    const float4* db = dec + (size_t)b * NN;
    const float*  cb = clsp + (size_t)b * NN * CC;
    const float*  nsb = g_neg_sum + (size_t)b * NN;
    const unsigned char* vb = g_valid + (size_t)b * NN;

    float tiou[10];
    unsigned long long tkey[10];
#pragma unroll
    for (int j = 0; j < 10; j++) { tiou[j] = 0.f; tkey[j] = 0xFFFFFFFFFFFFFFFFull; }
    int cnt = 0;

    for (int i = tid; i < NN; i += TPB2) {
        float4 pr = priors[i];
        float cx = pr.x, cy = pr.y, s = pr.z;
        float ibv = fminf(fminf(cx - g0, cy - g1), fminf(g2 - cx, g3 - cy));
        float r = 2.5f * s;
        float icv = fminf(fminf(cx - gcx + r, cy - gcy + r), fminf(gcx + r - cx, gcy + r - cy));
        bool in_both = (ibv > 0.f) && (icv > 0.f);

        float4 d = db[i];
        float iou = pair_iou(d, g0, g1, g2, g3);
        float iou_m = vb[i] ? iou : 0.f;
        if (iou_m > tiou[9]) {
            tiou[9] = iou_m;
#pragma unroll
            for (int j = 9; j > 0; j--)
                if (tiou[j] > tiou[j - 1]) { float t2 = tiou[j]; tiou[j] = tiou[j - 1]; tiou[j - 1] = t2; }
        }
        if (in_both) {
            // in_both => valid; unpenalized cost <= ~1350 < 1e5, so in_both priors
            // always outrank penalized ones in the top-k selection.
            cnt++;
            float p = clampp(cb[(size_t)i * CC + lbl]);
            float cost = pair_cost(nsb[i], p, iou);
            unsigned long long key = ((unsigned long long)f2mono(cost) << 32) | (unsigned)i;
            if (key < tkey[9]) {
                tkey[9] = key;
#pragma unroll
                for (int j = 9; j > 0; j--)
                    if (tkey[j] < tkey[j - 1]) { unsigned long long t2 = tkey[j]; tkey[j] = tkey[j - 1]; tkey[j - 1] = t2; }
            }
        }
    }

    __shared__ float s_iou[TPB2 * 10];
    __shared__ unsigned long long s_key[TPB2 * 10];
    __shared__ int s_cnt;
    if (tid == 0) s_cnt = 0;
    __syncthreads();
    atomicAdd(&s_cnt, cnt);
#pragma unroll
    for (int j = 0; j < 10; j++) s_iou[tid * 10 + j] = tiou[j];
    __syncthreads();

    // tree-merge top-10 IoUs (descending)
    for (int str = TPB2 >> 1; str >= 1; str >>= 1) {
        if (tid < str) {
            float* A  = &s_iou[tid * 10];
            float* Bp = &s_iou[(tid + str) * 10];
            float tmp[10]; int ia = 0, ib2 = 0;
#pragma unroll
            for (int t2 = 0; t2 < 10; t2++) {
                if (A[ia] >= Bp[ib2]) tmp[t2] = A[ia++]; else tmp[t2] = Bp[ib2++];
            }
#pragma unroll
            for (int t2 = 0; t2 < 10; t2++) A[t2] = tmp[t2];
        }
        __syncthreads();
    }

    int nib = s_cnt;
    if (nib < 10) {
        // exact fallback: full column with penalty terms (rare: columns with <10 in_both priors)
#pragma unroll
        for (int j = 0; j < 10; j++) tkey[j] = 0xFFFFFFFFFFFFFFFFull;
        for (int i = tid; i < NN; i += TPB2) {
            float4 pr = priors[i];
            float cx = pr.x, cy = pr.y, s = pr.z;
            float ibv = fminf(fminf(cx - g0, cy - g1), fminf(g2 - cx, g3 - cy));
            float r = 2.5f * s;
            float icv = fminf(fminf(cx - gcx + r, cy - gcy + r), fminf(gcx + r - cx, gcy + r - cy));
            bool in_both = (ibv > 0.f) && (icv > 0.f);
            float4 d = db[i];
            float iou = pair_iou(d, g0, g1, g2, g3);
            bool val = vb[i] != 0;
            float p = clampp(cb[(size_t)i * CC + lbl]);
            float cost = pair_cost(nsb[i], p, iou);
            if (!in_both) cost += 100000.0f;
            if (!val)     cost += 100000000.0f;
            unsigned long long key = ((unsigned long long)f2mono(cost) << 32) | (unsigned)i;
            if (key < tkey[9]) {
                tkey[9] = key;
#pragma unroll
                for (int j = 9; j > 0; j--)
                    if (tkey[j] < tkey[j - 1]) { unsigned long long t2 = tkey[j]; tkey[j] = tkey[j - 1]; tkey[j - 1] = t2; }
            }
        }
    }

#pragma unroll
    for (int j = 0; j < 10; j++) s_key[tid * 10 + j] = tkey[j];
    __syncthreads();
    // tree-merge cost keys (ascending; index in low bits => stable ties)
    for (int str = TPB2 >> 1; str >= 1; str >>= 1) {
        if (tid < str) {
            unsigned long long* A  = &s_key[tid * 10];
            unsigned long long* Bp = &s_key[(tid + str) * 10];
            unsigned long long tmp[10]; int ia = 0, ib2 = 0;
#pragma unroll
            for (int t2 = 0; t2 < 10; t2++) {
                if (A[ia] <= Bp[ib2]) tmp[t2] = A[ia++]; else tmp[t2] = Bp[ib2++];
            }
#pragma unroll
            for (int t2 = 0; t2 < 10; t2++) A[t2] = tmp[t2];
        }
        __syncthreads();
    }

    if (tid == 0) {
        float sum = 0.f;
#pragma unroll
        for (int j = 0; j < 10; j++) sum += s_iou[j];   // descending order, like top_k().sum()
        int dynk = (int)sum;                            // trunc toward 0 (sum >= 0)
        if (dynk < 1)  dynk = 1;
        if (dynk > 10) dynk = 10;
        unsigned bit = 1u << (g & 31);
        int word = g >> 5;
        for (int j = 0; j < dynk; j++) {
            unsigned long long k = s_key[j];
            if (k == 0xFFFFFFFFFFFFFFFFull) break;
            int i = (int)(k & 0xFFFFFFFFu);
            atomicOr(&g_match[((size_t)b * NN + i) * 4 + word], bit);
        }
    }
}

// ---------------- kernel 3: per-prior loss terms ----------------
__global__ void __launch_bounds__(256) k3_loss(
    const float4* __restrict__ priors,
    const float4* __restrict__ dec,
    const float*  __restrict__ clsp,
    const float*  __restrict__ regp,
    const float4* __restrict__ gtb,
    const int*    __restrict__ gtl)
{
    int idx = blockIdx.x * blockDim.x + threadIdx.x;
    int tid = threadIdx.x;
    float v_vfl = 0.f, v_gi = 0.f, v_df = 0.f, v_fg = 0.f, v_ts = 0.f;

    if (idx < BB * NN) {
        int b = idx / NN, i = idx - b * NN;
        unsigned m0 = g_match[(size_t)idx * 4 + 0];
        unsigned m1 = g_match[(size_t)idx * 4 + 1];
        unsigned m2 = g_match[(size_t)idx * 4 + 2];
        unsigned m3 = g_match[(size_t)idx * 4 + 3];
        int nm = __popc(m0) + __popc(m1) + __popc(m2) + __popc(m3);

        const float4* gb = gtb + (size_t)b * GG;
        float4 d = dec[idx];
        int mgt = 0;
        float mious = 0.f;

        if (nm == 1) {
            mgt = m0 ? (__ffs(m0) - 1)
                     : (m1 ? (31 + __ffs(m1))
                           : (m2 ? (63 + __ffs(m2)) : (95 + __ffs(m3))));
            float4 q = gb[mgt];
            mious = pair_iou(d, q.x, q.y, q.z, q.w);
        } else if (nm > 1) {
            // multi-match: reference replaces row with one_hot(argmin_g cost); first min wins
            float4 pr = priors[i];
            float cx = pr.x, cy = pr.y, s = pr.z;
            bool val = g_valid[idx] != 0;
            float ns = g_neg_sum[idx];
            const float* cp = clsp + (size_t)idx * CC;
            const int* gl = gtl + b * GG;
            float best = 3.4e38f; int bestg = 0;
            for (int g = 0; g < GG; g++) {
                float4 q = gb[g];
                float ibv = fminf(fminf(cx - q.x, cy - q.y), fminf(q.z - cx, q.w - cy));
                float gcx = (q.x + q.z) * 0.5f, gcy = (q.y + q.w) * 0.5f;
                float r = 2.5f * s;
                float icv = fminf(fminf(cx - gcx + r, cy - gcy + r), fminf(gcx + r - cx, gcy + r - cy));
                bool ib2 = (ibv > 0.f) && (icv > 0.f);
                float iou = pair_iou(d, q.x, q.y, q.z, q.w);
                float p = clampp(cp[gl[g]]);
                float cost = pair_cost(ns, p, iou);
                if (!ib2) cost += 100000.0f;
                if (!val) cost += 100000000.0f;
                if (cost < best) { best = cost; bestg = g; }
            }
            mgt = bestg;
            float4 q = gb[mgt];
            mious = pair_iou(d, q.x, q.y, q.z, q.w);
        }

        bool fg = nm > 0;
        float tscore = fg ? mious : 0.f;
        v_vfl = g_bg_vfl[idx];   // background VFL for all classes
        v_fg  = fg ? 1.f : 0.f;
        v_ts  = tscore;

        if (tscore > 0.f) {
            // VFL correction at matched label: swap background term for foreground term
            int lbl = gtl[b * GG + mgt];
            float p = clampp(clsp[(size_t)idx * CC + lbl]);
            float l1p = log1pf(-p);
            float t = tscore;
            float bce = -(t * logf(p) + (1.f - t) * l1p);
            v_vfl += bce * t - (-l1p * 0.75f * p * p);

            float4 q = gb[mgt];
            // GIoU loss
            {
                float tlx = fmaxf(d.x, q.x), tly = fmaxf(d.y, q.y);
                float brx = fminf(d.z, q.z), bry = fminf(d.w, q.w);
                float wx = fmaxf(brx - tlx, 0.f), wy = fmaxf(bry - tly, 0.f);
                float inter = wx * wy;
                float ap = fmaxf(d.z - d.x, 0.f) * fmaxf(d.w - d.y, 0.f);
                float at = fmaxf(q.z - q.x, 0.f) * fmaxf(q.w - q.y, 0.f);
                float un = ap + at - inter;
                float iou2 = inter / (un + 1e-16f);
                float c0 = fminf(d.x, q.x), c1 = fminf(d.y, q.y);
                float c2 = fmaxf(d.z, q.z), c3 = fmaxf(d.w, q.w);
                float cw = fmaxf(c2 - c0, 0.f), ch = fmaxf(c3 - c1, 0.f);
                float ac = cw * ch;
                v_gi = (1.f - (iou2 - (ac - un) / (ac + 1e-16f))) * t;
            }
            // DFL
            {
                float4 pr = priors[i];
                float cx = pr.x, cy = pr.y, s = pr.z;
                float ddv[4] = { (cx - q.x) / s, (cy - q.y) / s, (q.z - cx) / s, (q.w - cy) / s };
                const float* rp = regp + (size_t)idx * 32;
                float cesum = 0.f;
#pragma unroll
                for (int e = 0; e < 4; e++) {
                    float x[8];
#pragma unroll
                    for (int j = 0; j < 8; j++) x[j] = rp[e * 8 + j];
                    float mx = x[0];
#pragma unroll
                    for (int j = 1; j < 8; j++) mx = fmaxf(mx, x[j]);
                    float se = 0.f;
#pragma unroll
                    for (int j = 0; j < 8; j++) se += expf(x[j] - mx);
                    float lse = mx + logf(se);
                    float tt = fminf(fmaxf(ddv[e], 0.f), 6.9f);
                    int tl_ = (int)tt;
                    int tr_ = tl_ + 1 < 7 ? tl_ + 1 : 7;
                    float wl = (float)(tl_ + 1) - tt;
                    float wr = tt - (float)tl_;
                    cesum += -((x[tl_] - lse) * wl + (x[tr_] - lse) * wr);
                }
                v_df = cesum * t;
            }
        }
    }

    // block reduce 5 accumulators, one double atomic each
    __shared__ float sred[256];
    float vals[5] = { v_vfl, v_gi, v_df, v_fg, v_ts };
#pragma unroll
    for (int k = 0; k < 5; k++) {
        __syncthreads();
        sred[tid] = vals[k];
        __syncthreads();
        for (int st = 128; st; st >>= 1) {
            if (tid < st) sred[tid] += sred[tid + st];
            __syncthreads();
        }
        if (tid == 0) atomicAdd(&g_acc[k], (double)sred[0]);
    }
}

// ---------------- kernel 4: final combine ----------------
__global__ void k4_final(float* out) {
    double npos = g_acc[3] > 1.0 ? g_acc[3] : 1.0;
    double nsc  = g_acc[4] > 1.0 ? g_acc[4] : 1.0;
    out[0] = (float)(g_acc[0] / npos + 2.0 * g_acc[1] / nsc + 0.25 * g_acc[2] / nsc);
}

extern "C" void kernel_launch(void* const* d_in, const int* in_sizes, int n_in,
                              void* d_out, int out_size)
{
    const float4* priors = (const float4*)d_in[0];
    const float4* dec    = (const float4*)d_in[1];
    const float*  clsp   = (const float*)d_in[2];
    const float*  regp   = (const float*)d_in[3];
    const float4* gtb    = (const float4*)d_in[4];
    const int*    gtl    = (const int*)d_in[5];

    k1_prep<<<(BB * NN) / 8, 256>>>(priors, clsp, gtb);        // warp per prior: 272000 warps
    dim3 g2(GG, BB);
    k2_assign<<<g2, TPB2>>>(priors, dec, clsp, gtb, gtl);       // block per (b,g) column
    k3_loss<<<(BB * NN + 255) / 256, 256>>>(priors, dec, clsp, regp, gtb, gtl);
    k4_final<<<1, 1>>>((float*)d_out);
}

// round 4
// speedup vs baseline: 1.2773x; 1.2773x over previous
#include <cuda_runtime.h>
#include <cstdint>

#define BB 32
#define NN 8500
#define GG 128
#define CC 80
#define TPB2 128

// ---------------- scratch (__device__ globals: no allocation allowed) ----------------
__device__ float         g_neg_sum[BB * NN];     // sum_c -log(1-p)
__device__ float         g_bg_vfl [BB * NN];     // sum_c -log(1-p)*0.75*p^2
__device__ unsigned char g_valid  [BB * NN];     // prior valid flag
__device__ float4        g_mdec   [BB * NN];     // dec masked by valid (invalid -> -1e30 sentinel)
__device__ unsigned int  g_match  [BB * NN * 4]; // 128-bit match mask per prior
__device__ double        g_acc[5];               // vfl, giou, dfl, npos, nscore

__device__ __forceinline__ float clampp(float p) {
    return fminf(fmaxf(p, 1e-7f), 1.0f - 1e-7f);
}

// monotone float -> uint32 (total order matching float <)
__device__ __forceinline__ unsigned f2mono(float f) {
    unsigned u = __float_as_uint(f);
    return (u & 0x80000000u) ? ~u : (u | 0x80000000u);
}

__device__ __forceinline__ float pair_iou(float4 d, float g0, float g1, float g2, float g3) {
    float tlx = fmaxf(d.x, g0), tly = fmaxf(d.y, g1);
    float brx = fminf(d.z, g2), bry = fminf(d.w, g3);
    float wx = fmaxf(brx - tlx, 0.f), wy = fmaxf(bry - tly, 0.f);
    float inter = wx * wy;
    float aa  = (d.z - d.x) * (d.w - d.y);
    float ab2 = (g2 - g0) * (g3 - g1);
    return inter / (aa + ab2 - inter + 1e-16f);
}

// precise cost (used for ranking; composition matches reference)
__device__ __forceinline__ float pair_cost(float ns, float p, float iou) {
    float cls = ns + log1pf(-p) - logf(p);
    return cls + 3.f * (-logf(iou + 1e-8f));
}

// ---------------- kernel 1: per-prior prep (warp per prior) ----------------
__global__ void __launch_bounds__(256) k1_prep(
    const float4* __restrict__ priors,
    const float*  __restrict__ clsp,
    const float4* __restrict__ gtb)
{
    if (blockIdx.x == 0 && threadIdx.x < 5) g_acc[threadIdx.x] = 0.0;

    int w    = (blockIdx.x * blockDim.x + threadIdx.x) >> 5;
    int lane = threadIdx.x & 31;
    if (w >= BB * NN) return;
    int b = w / NN, i = w - b * NN;

    // 80 classes = 20 float4; lanes 0..19 each take one
    float a_ns = 0.f, a_bg = 0.f;
    if (lane < 20) {
        const float4* cp4 = (const float4*)(clsp + (size_t)w * CC);
        float4 v = cp4[lane];
        // clamp is a provable no-op for inputs in [1e-4, 1-1e-4]
        float l0 = __log2f(1.0f - v.x);
        float l1 = __log2f(1.0f - v.y);
        float l2 = __log2f(1.0f - v.z);
        float l3 = __log2f(1.0f - v.w);
        a_ns = ((l0 + l1) + (l2 + l3));
        a_bg = l0 * v.x * v.x + l1 * v.y * v.y + l2 * v.z * v.z + l3 * v.w * v.w;
    }
#pragma unroll
    for (int off = 16; off; off >>= 1) {
        a_ns += __shfl_down_sync(0xffffffffu, a_ns, off);
        a_bg += __shfl_down_sync(0xffffffffu, a_bg, off);
    }

    float4 pr = priors[i];
    float cx = pr.x, cy = pr.y, s = pr.z;
    const float4* gb = gtb + (size_t)b * GG;
    bool any = false;
#pragma unroll
    for (int g = lane; g < GG; g += 32) {
        float4 gq = gb[g];
        float ibv = fminf(fminf(cx - gq.x, cy - gq.y), fminf(gq.z - cx, gq.w - cy));
        float gcx = (gq.x + gq.z) * 0.5f, gcy = (gq.y + gq.w) * 0.5f;
        float r = 2.5f * s;
        float icv = fminf(fminf(cx - gcx + r, cy - gcy + r), fminf(gcx + r - cx, gcy + r - cy));
        any = any || (ibv > 0.f) || (icv > 0.f);
    }
    unsigned bal = __ballot_sync(0xffffffffu, any);
    if (lane == 0) {
        g_neg_sum[w] = -0.69314718f * a_ns;            // ln2
        g_bg_vfl[w]  = -0.75f * 0.69314718f * a_bg;
        g_valid[w]   = bal ? 1 : 0;
    }
    if (lane < 4) g_match[(size_t)w * 4 + lane] = 0u;
}

// ---------------- kernel 1b: masked dec ----------------
__global__ void __launch_bounds__(256) k1b_mask(const float4* __restrict__ dec)
{
    int idx = blockIdx.x * blockDim.x + threadIdx.x;
    if (idx >= BB * NN) return;
    float4 d = dec[idx];
    if (!g_valid[idx]) d = make_float4(-1e30f, -1e30f, -1e30f, -1e30f);
    g_mdec[idx] = d;
}

// exact integer bounds: smallest ix in [0,n] with (ix+0.5f)*s > L (n => empty)
__device__ __forceinline__ int lo_bnd(float L, float sf, int n) {
    int c = (int)floorf(__fdividef(L, sf)) - 1;
    if (c < 0) c = 0;
    while (c < n && !(((float)c + 0.5f) * sf > L)) c++;
    return c;
}
// largest ix in [-1,n-1] with (ix+0.5f)*s < H (-1 => empty)
__device__ __forceinline__ int hi_bnd(float H, float sf, int n) {
    int c = (int)floorf(__fdividef(H, sf)) + 1;
    if (c > n - 1) c = n - 1;
    while (c >= 0 && !(((float)c + 0.5f) * sf < H)) c--;
    return c;
}

template<int N_, int S_, int BASE_>
__device__ __forceinline__ void scan_level(
    int tid, const float4* __restrict__ md,
    float g0, float g1, float g2, float g3, float gcx, float gcy, float ab2,
    const float* __restrict__ nsb, const float* __restrict__ cb, int lbl,
    float* tiou, unsigned long long* tkey, int& cnt)
{
    constexpr int N2 = N_ * N_;
    constexpr int QY = TPB2 / N_;
    constexpr int RX = TPB2 % N_;
    const float sf = (float)S_;
    float Lx = fmaxf(g0, gcx - 2.5f * sf), Hx = fminf(g2, gcx + 2.5f * sf);
    float Ly = fmaxf(g1, gcy - 2.5f * sf), Hy = fminf(g3, gcy + 2.5f * sf);
    int xlo = lo_bnd(Lx, sf, N_), xhi = hi_bnd(Hx, sf, N_);
    int ylo = lo_bnd(Ly, sf, N_), yhi = hi_bnd(Hy, sf, N_);

    int iy = tid / N_, ix = tid - iy * N_;
    int t = tid;
    if (t >= N2) return;
    float4 d = md[BASE_ + t];
    for (; t < N2; t += TPB2) {
        int tn = t + TPB2;
        float4 dn = (tn < N2) ? md[BASE_ + tn] : make_float4(-1e30f, -1e30f, -1e30f, -1e30f);

        float wy = fminf(d.w, g3) - fmaxf(d.y, g1);
        float wx = fminf(d.z, g2) - fmaxf(d.x, g0);
        float iou = 0.f;
        if (fminf(wx, wy) > 0.f) {
            float inter = wx * wy;
            float aa = (d.z - d.x) * (d.w - d.y);
            iou = __fdividef(inter, aa + ab2 - inter + 1e-16f);
            if (iou > tiou[9]) {
                tiou[9] = iou;
#pragma unroll
                for (int j = 9; j > 0; j--)
                    if (tiou[j] > tiou[j - 1]) { float tt = tiou[j]; tiou[j] = tiou[j - 1]; tiou[j - 1] = tt; }
            }
        }
        if (ix >= xlo && ix <= xhi && iy >= ylo && iy <= yhi) {
            // in_both (boundary-exact) => valid; cost < 1e5 so always outranks penalized
            cnt++;
            int i = BASE_ + t;
            float p = clampp(cb[(size_t)i * CC + lbl]);
            float cost = pair_cost(nsb[i], p, iou);
            unsigned long long key = ((unsigned long long)f2mono(cost) << 32) | (unsigned)i;
            if (key < tkey[9]) {
                tkey[9] = key;
#pragma unroll
                for (int j = 9; j > 0; j--)
                    if (tkey[j] < tkey[j - 1]) { unsigned long long tt = tkey[j]; tkey[j] = tkey[j - 1]; tkey[j - 1] = tt; }
            }
        }
        d = dn;
        ix += RX; iy += QY;
        if (ix >= N_) { ix -= N_; iy += 1; }
    }
}

union SmemU {
    float              f[TPB2 * 10];
    unsigned long long k[TPB2 * 10];
};

// ---------------- kernel 2: SimOTA assignment, one block per (b,g) column ----------------
__global__ void __launch_bounds__(TPB2, 6) k2_assign(
    const float4* __restrict__ priors,
    const float4* __restrict__ dec,
    const float*  __restrict__ clsp,
    const float4* __restrict__ gtb,
    const int*    __restrict__ gtl)
{
    const int g = blockIdx.x, b = blockIdx.y;
    const int tid = threadIdx.x;

    float4 gq = gtb[(size_t)b * GG + g];
    const float g0 = gq.x, g1 = gq.y, g2 = gq.z, g3 = gq.w;
    const float gcx = (g0 + g2) * 0.5f, gcy = (g1 + g3) * 0.5f;
    const float ab2 = (g2 - g0) * (g3 - g1);
    const int   lbl = gtl[b * GG + g];
    const float4* md  = g_mdec + (size_t)b * NN;
    const float*  cb  = clsp + (size_t)b * NN * CC;
    const float*  nsb = g_neg_sum + (size_t)b * NN;

    float tiou[10];
    unsigned long long tkey[10];
#pragma unroll
    for (int j = 0; j < 10; j++) { tiou[j] = 0.f; tkey[j] = 0xFFFFFFFFFFFFFFFFull; }
    int cnt = 0;

    scan_level<80,  8,    0>(tid, md, g0, g1, g2, g3, gcx, gcy, ab2, nsb, cb, lbl, tiou, tkey, cnt);
    scan_level<40, 16, 6400>(tid, md, g0, g1, g2, g3, gcx, gcy, ab2, nsb, cb, lbl, tiou, tkey, cnt);
    scan_level<20, 32, 8000>(tid, md, g0, g1, g2, g3, gcx, gcy, ab2, nsb, cb, lbl, tiou, tkey, cnt);
    scan_level<10, 64, 8400>(tid, md, g0, g1, g2, g3, gcx, gcy, ab2, nsb, cb, lbl, tiou, tkey, cnt);

    __shared__ SmemU sh;
    __shared__ int s_cnt, s_dynk;
    if (tid == 0) s_cnt = 0;
    __syncthreads();
    atomicAdd(&s_cnt, cnt);
#pragma unroll
    for (int j = 0; j < 10; j++) sh.f[tid * 10 + j] = tiou[j];
    __syncthreads();

    // tree-merge top-10 IoUs (descending)
    for (int str = TPB2 >> 1; str >= 1; str >>= 1) {
        if (tid < str) {
            float* A  = &sh.f[tid * 10];
            float* Bp = &sh.f[(tid + str) * 10];
            float tmp[10]; int ia = 0, ib2 = 0;
#pragma unroll
            for (int t2 = 0; t2 < 10; t2++) {
                if (A[ia] >= Bp[ib2]) tmp[t2] = A[ia++]; else tmp[t2] = Bp[ib2++];
            }
#pragma unroll
            for (int t2 = 0; t2 < 10; t2++) A[t2] = tmp[t2];
        }
        __syncthreads();
    }
    if (tid == 0) {
        float sum = 0.f;
#pragma unroll
        for (int j = 0; j < 10; j++) sum += sh.f[j];
        int dynk = (int)sum;
        if (dynk < 1)  dynk = 1;
        if (dynk > 10) dynk = 10;
        s_dynk = dynk;
    }
    __syncthreads();   // protect sh.f reads before key phase reuses the union

    int nib = s_cnt;
    if (nib < 10) {
        // exact fallback: full column with penalty terms (rare)
        const unsigned char* vb = g_valid + (size_t)b * NN;
        const float4* db = dec + (size_t)b * NN;
#pragma unroll
        for (int j = 0; j < 10; j++) tkey[j] = 0xFFFFFFFFFFFFFFFFull;
        for (int i = tid; i < NN; i += TPB2) {
            float4 pr = priors[i];
            float cx = pr.x, cy = pr.y, s = pr.z;
            float ibv = fminf(fminf(cx - g0, cy - g1), fminf(g2 - cx, g3 - cy));
            float r = 2.5f * s;
            float icv = fminf(fminf(cx - gcx + r, cy - gcy + r), fminf(gcx + r - cx, gcy + r - cy));
            bool in_both = (ibv > 0.f) && (icv > 0.f);
            float4 d = db[i];
            float iou = pair_iou(d, g0, g1, g2, g3);
            bool val = vb[i] != 0;
            float p = clampp(cb[(size_t)i * CC + lbl]);
            float cost = pair_cost(nsb[i], p, iou);
            if (!in_both) cost += 100000.0f;
            if (!val)     cost += 100000000.0f;
            unsigned long long key = ((unsigned long long)f2mono(cost) << 32) | (unsigned)i;
            if (key < tkey[9]) {
                tkey[9] = key;
#pragma unroll
                for (int j = 9; j > 0; j--)
                    if (tkey[j] < tkey[j - 1]) { unsigned long long tt = tkey[j]; tkey[j] = tkey[j - 1]; tkey[j - 1] = tt; }
            }
        }
    }

#pragma unroll
    for (int j = 0; j < 10; j++) sh.k[tid * 10 + j] = tkey[j];
    __syncthreads();
    // tree-merge cost keys (ascending; index in low bits => stable ties)
    for (int str = TPB2 >> 1; str >= 1; str >>= 1) {
        if (tid < str) {
            unsigned long long* A  = &sh.k[tid * 10];
            unsigned long long* Bp = &sh.k[(tid + str) * 10];
            unsigned long long tmp[10]; int ia = 0, ib2 = 0;
#pragma unroll
            for (int t2 = 0; t2 < 10; t2++) {
                if (A[ia] <= Bp[ib2]) tmp[t2] = A[ia++]; else tmp[t2] = Bp[ib2++];
            }
#pragma unroll
            for (int t2 = 0; t2 < 10; t2++) A[t2] = tmp[t2];
        }
        __syncthreads();
    }

    if (tid == 0) {
        int dynk = s_dynk;
        unsigned bit = 1u << (g & 31);
        int word = g >> 5;
        for (int j = 0; j < dynk; j++) {
            unsigned long long k = sh.k[j];
            if (k == 0xFFFFFFFFFFFFFFFFull) break;
            int i = (int)(k & 0xFFFFFFFFu);
            atomicOr(&g_match[((size_t)b * NN + i) * 4 + word], bit);
        }
    }
}

// ---------------- kernel 3: per-prior loss terms ----------------
__global__ void __launch_bounds__(256) k3_loss(
    const float4* __restrict__ priors,
    const float4* __restrict__ dec,
    const float*  __restrict__ clsp,
    const float*  __restrict__ regp,
    const float4* __restrict__ gtb,
    const int*    __restrict__ gtl)
{
    int idx = blockIdx.x * blockDim.x + threadIdx.x;
    int tid = threadIdx.x;
    float v_vfl = 0.f, v_gi = 0.f, v_df = 0.f, v_fg = 0.f, v_ts = 0.f;

    if (idx < BB * NN) {
        int b = idx / NN, i = idx - b * NN;
        uint4 mw = *((const uint4*)&g_match[(size_t)idx * 4]);
        unsigned m0 = mw.x, m1 = mw.y, m2 = mw.z, m3 = mw.w;
        int nm = __popc(m0) + __popc(m1) + __popc(m2) + __popc(m3);

        const float4* gb = gtb + (size_t)b * GG;
        float4 d = dec[idx];
        int mgt = 0;
        float mious = 0.f;

        if (nm == 1) {
            mgt = m0 ? (__ffs(m0) - 1)
                     : (m1 ? (31 + __ffs(m1))
                           : (m2 ? (63 + __ffs(m2)) : (95 + __ffs(m3))));
            float4 q = gb[mgt];
            mious = pair_iou(d, q.x, q.y, q.z, q.w);
        } else if (nm > 1) {
            // multi-match: reference replaces row with one_hot(argmin_g cost); first min wins
            float4 pr = priors[i];
            float cx = pr.x, cy = pr.y, s = pr.z;
            bool val = g_valid[idx] != 0;
            float ns = g_neg_sum[idx];
            const float* cp = clsp + (size_t)idx * CC;
            const int* gl = gtl + b * GG;
            float best = 3.4e38f; int bestg = 0;
            for (int g = 0; g < GG; g++) {
                float4 q = gb[g];
                float ibv = fminf(fminf(cx - q.x, cy - q.y), fminf(q.z - cx, q.w - cy));
                float gcx = (q.x + q.z) * 0.5f, gcy = (q.y + q.w) * 0.5f;
                float r = 2.5f * s;
                float icv = fminf(fminf(cx - gcx + r, cy - gcy + r), fminf(gcx + r - cx, gcy + r - cy));
                bool ib2 = (ibv > 0.f) && (icv > 0.f);
                float iou = pair_iou(d, q.x, q.y, q.z, q.w);
                float p = clampp(cp[gl[g]]);
                float cost = pair_cost(ns, p, iou);
                if (!ib2) cost += 100000.0f;
                if (!val) cost += 100000000.0f;
                if (cost < best) { best = cost; bestg = g; }
            }
            mgt = bestg;
            float4 q = gb[mgt];
            mious = pair_iou(d, q.x, q.y, q.z, q.w);
        }

        bool fg = nm > 0;
        float tscore = fg ? mious : 0.f;
        v_vfl = g_bg_vfl[idx];   // background VFL for all classes
        v_fg  = fg ? 1.f : 0.f;
        v_ts  = tscore;

        if (tscore > 0.f) {
            // VFL correction at matched label
            int lbl = gtl[b * GG + mgt];
            float p = clampp(clsp[(size_t)idx * CC + lbl]);
            float l1p = log1pf(-p);
            float t = tscore;
            float bce = -(t * logf(p) + (1.f - t) * l1p);
            v_vfl += bce * t - (-l1p * 0.75f * p * p);

            float4 q = gb[mgt];
            // GIoU loss
            {
                float tlx = fmaxf(d.x, q.x), tly = fmaxf(d.y, q.y);
                float brx = fminf(d.z, q.z), bry = fminf(d.w, q.w);
                float wx = fmaxf(brx - tlx, 0.f), wy = fmaxf(bry - tly, 0.f);
                float inter = wx * wy;
                float ap = fmaxf(d.z - d.x, 0.f) * fmaxf(d.w - d.y, 0.f);
                float at = fmaxf(q.z - q.x, 0.f) * fmaxf(q.w - q.y, 0.f);
                float un = ap + at - inter;
                float iou2 = inter / (un + 1e-16f);
                float c0 = fminf(d.x, q.x), c1 = fminf(d.y, q.y);
                float c2 = fmaxf(d.z, q.z), c3 = fmaxf(d.w, q.w);
                float cw = fmaxf(c2 - c0, 0.f), ch = fmaxf(c3 - c1, 0.f);
                float ac = cw * ch;
                v_gi = (1.f - (iou2 - (ac - un) / (ac + 1e-16f))) * t;
            }
            // DFL
            {
                float4 pr = priors[i];
                float cx = pr.x, cy = pr.y, s = pr.z;
                float ddv[4] = { (cx - q.x) / s, (cy - q.y) / s, (q.z - cx) / s, (q.w - cy) / s };
                const float* rp = regp + (size_t)idx * 32;
                float cesum = 0.f;
#pragma unroll
                for (int e = 0; e < 4; e++) {
                    float x[8];
#pragma unroll
                    for (int j = 0; j < 8; j++) x[j] = rp[e * 8 + j];
                    float mx = x[0];
#pragma unroll
                    for (int j = 1; j < 8; j++) mx = fmaxf(mx, x[j]);
                    float se = 0.f;
#pragma unroll
                    for (int j = 0; j < 8; j++) se += expf(x[j] - mx);
                    float lse = mx + logf(se);
                    float tt = fminf(fmaxf(ddv[e], 0.f), 6.9f);
                    int tl_ = (int)tt;
                    int tr_ = tl_ + 1 < 7 ? tl_ + 1 : 7;
                    float wl = (float)(tl_ + 1) - tt;
                    float wr = tt - (float)tl_;
                    cesum += -((x[tl_] - lse) * wl + (x[tr_] - lse) * wr);
                }
                v_df = cesum * t;
            }
        }
    }

    // block reduce 5 accumulators
    __shared__ float sred[256];
    float vals[5] = { v_vfl, v_gi, v_df, v_fg, v_ts };
#pragma unroll
    for (int k = 0; k < 5; k++) {
        __syncthreads();
        sred[tid] = vals[k];
        __syncthreads();
        for (int st = 128; st; st >>= 1) {
            if (tid < st) sred[tid] += sred[tid + st];
            __syncthreads();
        }
        if (tid == 0) atomicAdd(&g_acc[k], (double)sred[0]);
    }
}

// ---------------- kernel 4: final combine ----------------
__global__ void k4_final(float* out) {
    double npos = g_acc[3] > 1.0 ? g_acc[3] : 1.0;
    double nsc  = g_acc[4] > 1.0 ? g_acc[4] : 1.0;
    out[0] = (float)(g_acc[0] / npos + 2.0 * g_acc[1] / nsc + 0.25 * g_acc[2] / nsc);
}

extern "C" void kernel_launch(void* const* d_in, const int* in_sizes, int n_in,
                              void* d_out, int out_size)
{
    const float4* priors = (const float4*)d_in[0];
    const float4* dec    = (const float4*)d_in[1];
    const float*  clsp   = (const float*)d_in[2];
    const float*  regp   = (const float*)d_in[3];
    const float4* gtb    = (const float4*)d_in[4];
    const int*    gtl    = (const int*)d_in[5];

    k1_prep<<<(BB * NN) / 8, 256>>>(priors, clsp, gtb);
    k1b_mask<<<(BB * NN + 255) / 256, 256>>>(dec);
    dim3 g2(GG, BB);
    k2_assign<<<g2, TPB2>>>(priors, dec, clsp, gtb, gtl);
    k3_loss<<<(BB * NN + 255) / 256, 256>>>(priors, dec, clsp, regp, gtb, gtl);
    k4_final<<<1, 1>>>((float*)d_out);
}

// round 11
// speedup vs baseline: 1.6212x; 1.2692x over previous
#include <cuda_runtime.h>
#include <cstdint>

#define BB 32
#define NN 8500
#define GG 128
#define CC 80
#define TPB2 128

// ---------------- scratch (__device__ globals: no allocation allowed) ----------------
__device__ float         g_neg_sum[BB * NN];     // sum_c -log(1-p)
__device__ float         g_bg_vfl [BB * NN];     // sum_c -log(1-p)*0.75*p^2
__device__ unsigned char g_valid  [BB * NN];     // prior valid flag
__device__ float4        g_mdec   [BB * NN];     // dec masked by valid (invalid -> -1e30 sentinel)
__device__ unsigned int  g_match  [BB * NN * 4]; // 128-bit match mask per prior
__device__ unsigned long long g_best[BB * NN];   // min over in_both g of (mono(cost)<<32 | g)
__device__ double        g_acc[5];               // vfl, giou, dfl, npos, nscore

__device__ __forceinline__ float clampp(float p) {
    return fminf(fmaxf(p, 1e-7f), 1.0f - 1e-7f);
}

// monotone float -> uint32 (total order matching float <)
__device__ __forceinline__ unsigned f2mono(float f) {
    unsigned u = __float_as_uint(f);
    return (u & 0x80000000u) ? ~u : (u | 0x80000000u);
}

__device__ __forceinline__ float pair_iou(float4 d, float g0, float g1, float g2, float g3) {
    float tlx = fmaxf(d.x, g0), tly = fmaxf(d.y, g1);
    float brx = fminf(d.z, g2), bry = fminf(d.w, g3);
    float wx = fmaxf(brx - tlx, 0.f), wy = fmaxf(bry - tly, 0.f);
    float inter = wx * wy;
    float aa  = (d.z - d.x) * (d.w - d.y);
    float ab2 = (g2 - g0) * (g3 - g1);
    return inter / (aa + ab2 - inter + 1e-16f);
}

// precise cost (used only in rare k3 sentinel fallback)
__device__ __forceinline__ float pair_cost(float ns, float p, float iou) {
    float cls = ns + log1pf(-p) - logf(p);
    return cls + 3.f * (-logf(iou + 1e-8f));
}
// fast cost for selection (ranking-only; gaps >> 1e-6 perturbation)
__device__ __forceinline__ float pair_cost_fast(float ns, float p, float iou) {
    return ns + __logf(__fdividef(1.0f - p, p)) - 3.f * __logf(iou + 1e-8f);
}

// ---------------- kernel 1: per-prior prep (warp per prior; masked dec fused) ----------------
__global__ void __launch_bounds__(256) k1_prep(
    const float4* __restrict__ priors,
    const float*  __restrict__ clsp,
    const float4* __restrict__ gtb,
    const float4* __restrict__ dec)
{
    if (blockIdx.x == 0 && threadIdx.x < 5) g_acc[threadIdx.x] = 0.0;

    int w    = (blockIdx.x * blockDim.x + threadIdx.x) >> 5;
    int lane = threadIdx.x & 31;
    if (w >= BB * NN) return;
    int b = w / NN, i = w - b * NN;

    // 80 classes = 20 float4; lanes 0..19 each take one
    float a_ns = 0.f, a_bg = 0.f;
    if (lane < 20) {
        const float4* cp4 = (const float4*)(clsp + (size_t)w * CC);
        float4 v = cp4[lane];
        float l0 = __log2f(1.0f - v.x);
        float l1 = __log2f(1.0f - v.y);
        float l2 = __log2f(1.0f - v.z);
        float l3 = __log2f(1.0f - v.w);
        a_ns = ((l0 + l1) + (l2 + l3));
        a_bg = l0 * v.x * v.x + l1 * v.y * v.y + l2 * v.z * v.z + l3 * v.w * v.w;
    }
#pragma unroll
    for (int off = 16; off; off >>= 1) {
        a_ns += __shfl_down_sync(0xffffffffu, a_ns, off);
        a_bg += __shfl_down_sync(0xffffffffu, a_bg, off);
    }

    float4 pr = priors[i];
    float cx = pr.x, cy = pr.y, s = pr.z;
    const float4* gb = gtb + (size_t)b * GG;
    bool any = false;
#pragma unroll
    for (int g = lane; g < GG; g += 32) {
        float4 gq = gb[g];
        float ibv = fminf(fminf(cx - gq.x, cy - gq.y), fminf(gq.z - cx, gq.w - cy));
        float gcx = (gq.x + gq.z) * 0.5f, gcy = (gq.y + gq.w) * 0.5f;
        float r = 2.5f * s;
        float icv = fminf(fminf(cx - gcx + r, cy - gcy + r), fminf(gcx + r - cx, gcy + r - cy));
        any = any || (ibv > 0.f) || (icv > 0.f);
    }
    unsigned bal = __ballot_sync(0xffffffffu, any);
    if (lane == 0) {
        g_neg_sum[w] = -0.69314718f * a_ns;            // ln2
        g_bg_vfl[w]  = -0.75f * 0.69314718f * a_bg;
        g_valid[w]   = bal ? 1 : 0;
        float4 d = dec[w];
        if (!bal) d = make_float4(-1e30f, -1e30f, -1e30f, -1e30f);
        g_mdec[w] = d;
    }
    if (lane < 4) g_match[(size_t)w * 4 + lane] = 0u;
    if (lane == 4) g_best[w] = 0xFFFFFFFFFFFFFFFFull;
}

// exact integer bounds: smallest ix in [0,n] with (ix+0.5f)*s > L (n => empty)
__device__ __forceinline__ int lo_bnd(float L, float sf, int n) {
    int c = (int)floorf(__fdividef(L, sf)) - 1;
    if (c < 0) c = 0;
    while (c < n && !(((float)c + 0.5f) * sf > L)) c++;
    return c;
}
// largest ix in [-1,n-1] with (ix+0.5f)*s < H (-1 => empty)
__device__ __forceinline__ int hi_bnd(float H, float sf, int n) {
    int c = (int)floorf(__fdividef(H, sf)) + 1;
    if (c > n - 1) c = n - 1;
    while (c >= 0 && !(((float)c + 0.5f) * sf < H)) c--;
    return c;
}

template<int N_, int S_, int BASE_>
__device__ __forceinline__ void scan_level(
    int tid, int g, const float4* __restrict__ md,
    float g0, float g1, float g2, float g3, float gcx, float gcy, float ab2,
    const float* __restrict__ nsb, const float* __restrict__ cb, int lbl,
    unsigned long long* __restrict__ bestb,
    float* tiou, unsigned long long* tkey, int& cnt)
{
    constexpr int N2 = N_ * N_;
    constexpr int QY = TPB2 / N_;
    constexpr int RX = TPB2 % N_;
    const float sf = (float)S_;
    float Lx = fmaxf(g0, gcx - 2.5f * sf), Hx = fminf(g2, gcx + 2.5f * sf);
    float Ly = fmaxf(g1, gcy - 2.5f * sf), Hy = fminf(g3, gcy + 2.5f * sf);
    int xlo = lo_bnd(Lx, sf, N_), xhi = hi_bnd(Hx, sf, N_);
    int ylo = lo_bnd(Ly, sf, N_), yhi = hi_bnd(Hy, sf, N_);

    int iy = tid / N_, ix = tid - iy * N_;
    int t = tid;
    if (t >= N2) return;
    float4 d = md[BASE_ + t];
    for (; t < N2; t += TPB2) {
        int tn = t + TPB2;
        float4 dn = (tn < N2) ? md[BASE_ + tn] : make_float4(-1e30f, -1e30f, -1e30f, -1e30f);

        float wy = fminf(d.w, g3) - fmaxf(d.y, g1);
        float wx = fminf(d.z, g2) - fmaxf(d.x, g0);
        float iou = 0.f;
        if (fminf(wx, wy) > 0.f) {
            float inter = wx * wy;
            float aa = (d.z - d.x) * (d.w - d.y);
            iou = __fdividef(inter, aa + ab2 - inter + 1e-16f);
            if (iou > tiou[9]) {
                tiou[9] = iou;
#pragma unroll
                for (int j = 9; j > 0; j--)
                    if (tiou[j] > tiou[j - 1]) { float tt = tiou[j]; tiou[j] = tiou[j - 1]; tiou[j - 1] = tt; }
            }
        }
        if (ix >= xlo && ix <= xhi && iy >= ylo && iy <= yhi) {
            // in_both (boundary-exact) => valid; cost < 1e5 so always outranks penalized
            cnt++;
            int i = BASE_ + t;
            float p = clampp(cb[(size_t)i * CC + lbl]);
            float cost = pair_cost_fast(nsb[i], p, iou);
            unsigned mono = f2mono(cost);
            unsigned long long key = ((unsigned long long)mono << 32) | (unsigned)i;
            if (key < tkey[9]) {
                tkey[9] = key;
#pragma unroll
                for (int j = 9; j > 0; j--)
                    if (tkey[j] < tkey[j - 1]) { unsigned long long tt = tkey[j]; tkey[j] = tkey[j - 1]; tkey[j - 1] = tt; }
            }
            // record per-prior argmin over g (ties -> lowest g, matching jnp.argmin)
            atomicMin(&bestb[i], ((unsigned long long)mono << 32) | (unsigned)g);
        }
        d = dn;
        ix += RX; iy += QY;
        if (ix >= N_) { ix -= N_; iy += 1; }
    }
}

union SmemU {
    float              f[TPB2 * 10];
    unsigned long long k[TPB2 * 10];
};

// ---------------- kernel 2: SimOTA assignment, one block per (b,g) column ----------------
__global__ void __launch_bounds__(TPB2, 5) k2_assign(
    const float4* __restrict__ priors,
    const float4* __restrict__ dec,
    const float*  __restrict__ clsp,
    const float4* __restrict__ gtb,
    const int*    __restrict__ gtl)
{
    const int g = blockIdx.x, b = blockIdx.y;
    const int tid = threadIdx.x;

    float4 gq = gtb[(size_t)b * GG + g];
    const float g0 = gq.x, g1 = gq.y, g2 = gq.z, g3 = gq.w;
    const float gcx = (g0 + g2) * 0.5f, gcy = (g1 + g3) * 0.5f;
    const float ab2 = (g2 - g0) * (g3 - g1);
    const int   lbl = gtl[b * GG + g];
    const float4* md  = g_mdec + (size_t)b * NN;
    const float*  cb  = clsp + (size_t)b * NN * CC;
    const float*  nsb = g_neg_sum + (size_t)b * NN;
    unsigned long long* bestb = g_best + (size_t)b * NN;

    float tiou[10];
    unsigned long long tkey[10];
#pragma unroll
    for (int j = 0; j < 10; j++) { tiou[j] = 0.f; tkey[j] = 0xFFFFFFFFFFFFFFFFull; }
    int cnt = 0;

    scan_level<80,  8,    0>(tid, g, md, g0, g1, g2, g3, gcx, gcy, ab2, nsb, cb, lbl, bestb, tiou, tkey, cnt);
    scan_level<40, 16, 6400>(tid, g, md, g0, g1, g2, g3, gcx, gcy, ab2, nsb, cb, lbl, bestb, tiou, tkey, cnt);
    scan_level<20, 32, 8000>(tid, g, md, g0, g1, g2, g3, gcx, gcy, ab2, nsb, cb, lbl, bestb, tiou, tkey, cnt);
    scan_level<10, 64, 8400>(tid, g, md, g0, g1, g2, g3, gcx, gcy, ab2, nsb, cb, lbl, bestb, tiou, tkey, cnt);

    __shared__ SmemU sh;
    __shared__ int s_cnt, s_dynk;
    if (tid == 0) s_cnt = 0;
    __syncthreads();
    atomicAdd(&s_cnt, cnt);
#pragma unroll
    for (int j = 0; j < 10; j++) sh.f[tid * 10 + j] = tiou[j];
    __syncthreads();

    // tree-merge top-10 IoUs (descending)
    for (int str = TPB2 >> 1; str >= 1; str >>= 1) {
        if (tid < str) {
            float* A  = &sh.f[tid * 10];
            float* Bp = &sh.f[(tid + str) * 10];
            float tmp[10]; int ia = 0, ib2 = 0;
#pragma unroll
            for (int t2 = 0; t2 < 10; t2++) {
                if (A[ia] >= Bp[ib2]) tmp[t2] = A[ia++]; else tmp[t2] = Bp[ib2++];
            }
#pragma unroll
            for (int t2 = 0; t2 < 10; t2++) A[t2] = tmp[t2];
        }
        __syncthreads();
    }
    if (tid == 0) {
        float sum = 0.f;
#pragma unroll
        for (int j = 0; j < 10; j++) sum += sh.f[j];
        int dynk = (int)sum;
        if (dynk < 1)  dynk = 1;
        if (dynk > 10) dynk = 10;
        s_dynk = dynk;
    }
    __syncthreads();   // protect sh.f reads before key phase reuses the union

    int nib = s_cnt;
    if (nib < 10) {
        // exact fallback: full column with penalty terms (columns with <10 in_both priors)
        const unsigned char* vb = g_valid + (size_t)b * NN;
        const float4* db = dec + (size_t)b * NN;
#pragma unroll
        for (int j = 0; j < 10; j++) tkey[j] = 0xFFFFFFFFFFFFFFFFull;
        for (int i = tid; i < NN; i += TPB2) {
            float4 pr = priors[i];
            float cx = pr.x, cy = pr.y, s = pr.z;
            float ibv = fminf(fminf(cx - g0, cy - g1), fminf(g2 - cx, g3 - cy));
            float r = 2.5f * s;
            float icv = fminf(fminf(cx - gcx + r, cy - gcy + r), fminf(gcx + r - cx, gcy + r - cy));
            bool in_both = (ibv > 0.f) && (icv > 0.f);
            float4 d = db[i];
            float iou = pair_iou(d, g0, g1, g2, g3);
            bool val = vb[i] != 0;
            float p = clampp(cb[(size_t)i * CC + lbl]);
            float cost = pair_cost_fast(nsb[i], p, iou);
            if (!in_both) cost += 100000.0f;
            if (!val)     cost += 100000000.0f;
            unsigned long long key = ((unsigned long long)f2mono(cost) << 32) | (unsigned)i;
            if (key < tkey[9]) {
                tkey[9] = key;
#pragma unroll
                for (int j = 9; j > 0; j--)
                    if (tkey[j] < tkey[j - 1]) { unsigned long long tt = tkey[j]; tkey[j] = tkey[j - 1]; tkey[j - 1] = tt; }
            }
        }
    }

#pragma unroll
    for (int j = 0; j < 10; j++) sh.k[tid * 10 + j] = tkey[j];
    __syncthreads();
    // tree-merge cost keys (ascending; index in low bits => stable ties)
    for (int str = TPB2 >> 1; str >= 1; str >>= 1) {
        if (tid < str) {
            unsigned long long* A  = &sh.k[tid * 10];
            unsigned long long* Bp = &sh.k[(tid + str) * 10];
            unsigned long long tmp[10]; int ia = 0, ib2 = 0;
#pragma unroll
            for (int t2 = 0; t2 < 10; t2++) {
                if (A[ia] <= Bp[ib2]) tmp[t2] = A[ia++]; else tmp[t2] = Bp[ib2++];
            }
#pragma unroll
            for (int t2 = 0; t2 < 10; t2++) A[t2] = tmp[t2];
        }
        __syncthreads();
    }

    if (tid == 0) {
        int dynk = s_dynk;
        unsigned bit = 1u << (g & 31);
        int word = g >> 5;
        for (int j = 0; j < dynk; j++) {
            unsigned long long k = sh.k[j];
            if (k == 0xFFFFFFFFFFFFFFFFull) break;
            int i = (int)(k & 0xFFFFFFFFu);
            atomicOr(&g_match[((size_t)b * NN + i) * 4 + word], bit);
        }
    }
}

// ---------------- kernel 3: per-prior loss terms ----------------
__global__ void __launch_bounds__(256) k3_loss(
    const float4* __restrict__ priors,
    const float4* __restrict__ dec,
    const float*  __restrict__ clsp,
    const float*  __restrict__ regp,
    const float4* __restrict__ gtb,
    const int*    __restrict__ gtl)
{
    int idx = blockIdx.x * blockDim.x + threadIdx.x;
    int tid = threadIdx.x;
    float v_vfl = 0.f, v_gi = 0.f, v_df = 0.f, v_fg = 0.f, v_ts = 0.f;

    if (idx < BB * NN) {
        int b = idx / NN, i = idx - b * NN;
        uint4 mw = *((const uint4*)&g_match[(size_t)idx * 4]);
        unsigned m0 = mw.x, m1 = mw.y, m2 = mw.z, m3 = mw.w;
        int nm = __popc(m0) + __popc(m1) + __popc(m2) + __popc(m3);

        const float4* gb = gtb + (size_t)b * GG;
        float4 d = dec[idx];
        int mgt = 0;
        float mious = 0.f;

        if (nm == 1) {
            mgt = m0 ? (__ffs(m0) - 1)
                     : (m1 ? (31 + __ffs(m1))
                           : (m2 ? (63 + __ffs(m2)) : (95 + __ffs(m3))));
            float4 q = gb[mgt];
            mious = pair_iou(d, q.x, q.y, q.z, q.w);
        } else if (nm > 1) {
            // multi-match: argmin_g cost recorded by k2 over in_both columns
            // (global argmin provably lands there: unpenalized cost in [0,~1350] < 1e5)
            unsigned long long bst = g_best[idx];
            if (bst != 0xFFFFFFFFFFFFFFFFull) {
                mgt = (int)(bst & 0xFFFFFFFFu);
            } else {
                // sentinel: matched only via penalized fallback selections; full argmin
                float4 pr = priors[i];
                float cx = pr.x, cy = pr.y, s = pr.z;
                bool val = g_valid[idx] != 0;
                float ns = g_neg_sum[idx];
                const float* cp = clsp + (size_t)idx * CC;
                const int* gl = gtl + b * GG;
                float best = 3.4e38f; int bestg = 0;
                for (int g = 0; g < GG; g++) {
                    float4 q = gb[g];
                    float ibv = fminf(fminf(cx - q.x, cy - q.y), fminf(q.z - cx, q.w - cy));
                    float gcx = (q.x + q.z) * 0.5f, gcy = (q.y + q.w) * 0.5f;
                    float r = 2.5f * s;
                    float icv = fminf(fminf(cx - gcx + r, cy - gcy + r), fminf(gcx + r - cx, gcy + r - cy));
                    bool ib2 = (ibv > 0.f) && (icv > 0.f);
                    float iou = pair_iou(d, q.x, q.y, q.z, q.w);
                    float p = clampp(cp[gl[g]]);
                    float cost = pair_cost(ns, p, iou);
                    if (!ib2) cost += 100000.0f;
                    if (!val) cost += 100000000.0f;
                    if (cost < best) { best = cost; bestg = g; }
                }
                mgt = bestg;
            }
            float4 q = gb[mgt];
            mious = pair_iou(d, q.x, q.y, q.z, q.w);
        }

        bool fg = nm > 0;
        float tscore = fg ? mious : 0.f;
        v_vfl = g_bg_vfl[idx];   // background VFL for all classes
        v_fg  = fg ? 1.f : 0.f;
        v_ts  = tscore;

        if (tscore > 0.f) {
            // VFL correction at matched label
            int lbl = gtl[b * GG + mgt];
            float p = clampp(clsp[(size_t)idx * CC + lbl]);
            float l1p = log1pf(-p);
            float t = tscore;
            float bce = -(t * logf(p) + (1.f - t) * l1p);
            v_vfl += bce * t - (-l1p * 0.75f * p * p);

            float4 q = gb[mgt];
            // GIoU loss
            {
                float tlx = fmaxf(d.x, q.x), tly = fmaxf(d.y, q.y);
                float brx = fminf(d.z, q.z), bry = fminf(d.w, q.w);
                float wx = fmaxf(brx - tlx, 0.f), wy = fmaxf(bry - tly, 0.f);
                float inter = wx * wy;
                float ap = fmaxf(d.z - d.x, 0.f) * fmaxf(d.w - d.y, 0.f);
                float at = fmaxf(q.z - q.x, 0.f) * fmaxf(q.w - q.y, 0.f);
                float un = ap + at - inter;
                float iou2 = inter / (un + 1e-16f);
                float c0 = fminf(d.x, q.x), c1 = fminf(d.y, q.y);
                float c2 = fmaxf(d.z, q.z), c3 = fmaxf(d.w, q.w);
                float cw = fmaxf(c2 - c0, 0.f), ch = fmaxf(c3 - c1, 0.f);
                float ac = cw * ch;
                v_gi = (1.f - (iou2 - (ac - un) / (ac + 1e-16f))) * t;
            }
            // DFL
            {
                float4 pr = priors[i];
                float cx = pr.x, cy = pr.y, s = pr.z;
                float ddv[4] = { (cx - q.x) / s, (cy - q.y) / s, (q.z - cx) / s, (q.w - cy) / s };
                const float* rp = regp + (size_t)idx * 32;
                float cesum = 0.f;
#pragma unroll
                for (int e = 0; e < 4; e++) {
                    float x[8];
#pragma unroll
                    for (int j = 0; j < 8; j++) x[j] = rp[e * 8 + j];
                    float mx = x[0];
#pragma unroll
                    for (int j = 1; j < 8; j++) mx = fmaxf(mx, x[j]);
                    float se = 0.f;
#pragma unroll
                    for (int j = 0; j < 8; j++) se += expf(x[j] - mx);
                    float lse = mx + logf(se);
                    float tt = fminf(fmaxf(ddv[e], 0.f), 6.9f);
                    int tl_ = (int)tt;
                    int tr_ = tl_ + 1 < 7 ? tl_ + 1 : 7;
                    float wl = (float)(tl_ + 1) - tt;
                    float wr = tt - (float)tl_;
                    cesum += -((x[tl_] - lse) * wl + (x[tr_] - lse) * wr);
                }
                v_df = cesum * t;
            }
        }
    }

    // reduce 5 accumulators: warp shuffle + one sync + warp 0 finish
    float vals[5] = { v_vfl, v_gi, v_df, v_fg, v_ts };
    int lane = tid & 31, wid = tid >> 5;
    __shared__ float swr[8][5];
#pragma unroll
    for (int k = 0; k < 5; k++) {
        float v = vals[k];
#pragma unroll
        for (int off = 16; off; off >>= 1) v += __shfl_down_sync(0xffffffffu, v, off);
        if (lane == 0) swr[wid][k] = v;
    }
    __syncthreads();
    if (wid == 0) {
#pragma unroll
        for (int k = 0; k < 5; k++) {
            float v = (lane < 8) ? swr[lane][k] : 0.f;
#pragma unroll
            for (int off = 4; off; off >>= 1) v += __shfl_down_sync(0xffffffffu, v, off);
            if (lane == 0) atomicAdd(&g_acc[k], (double)v);
        }
    }
}

// ---------------- kernel 4: final combine ----------------
__global__ void k4_final(float* out) {
    double npos = g_acc[3] > 1.0 ? g_acc[3] : 1.0;
    double nsc  = g_acc[4] > 1.0 ? g_acc[4] : 1.0;
    out[0] = (float)(g_acc[0] / npos + 2.0 * g_acc[1] / nsc + 0.25 * g_acc[2] / nsc);
}

extern "C" void kernel_launch(void* const* d_in, const int* in_sizes, int n_in,
                              void* d_out, int out_size)
{
    const float4* priors = (const float4*)d_in[0];
    const float4* dec    = (const float4*)d_in[1];
    const float*  clsp   = (const float*)d_in[2];
    const float*  regp   = (const float*)d_in[3];
    const float4* gtb    = (const float4*)d_in[4];
    const int*    gtl    = (const int*)d_in[5];

    k1_prep<<<(BB * NN) / 8, 256>>>(priors, clsp, gtb, dec);
    dim3 g2(GG, BB);
    k2_assign<<<g2, TPB2>>>(priors, dec, clsp, gtb, gtl);
    k3_loss<<<(BB * NN + 255) / 256, 256>>>(priors, dec, clsp, regp, gtb, gtl);
    k4_final<<<1, 1>>>((float*)d_out);
}

// round 12
// speedup vs baseline: 1.8766x; 1.1575x over previous
#include <cuda_runtime.h>
#include <cstdint>

#define BB 32
#define NN 8500
#define GG 128
#define CC 80
#define TPB2 128
#define NSTRIP 68

// ---------------- scratch (__device__ globals: no allocation allowed) ----------------
__device__ float         g_neg_sum[BB * NN];     // sum_c -log(1-p)
__device__ float         g_bg_vfl [BB * NN];     // sum_c -log(1-p)*0.75*p^2
__device__ unsigned char g_valid  [BB * NN];     // prior valid flag
__device__ float4        g_mdec   [BB * NN];     // dec masked by valid (invalid -> -1e30 sentinel)
__device__ float4        g_aabb   [BB * NSTRIP]; // per-strip AABB of valid decoded boxes (mnx,mny,mxx,mxy)
__device__ unsigned int  g_match  [BB * NN * 4]; // 128-bit match mask per prior
__device__ unsigned long long g_best[BB * NN];   // min over in_both g of (mono(cost)<<32 | g)
__device__ double        g_acc[5];               // vfl, giou, dfl, npos, nscore

// strip/level tables: levels have 80x80,40x40,20x20,10x10 cells at stride 8,16,32,64
__device__ __forceinline__ int lvl_of(int s)   { return (s < 50) ? 0 : (s < 63) ? 1 : (s < 67) ? 2 : 3; }
__device__ __forceinline__ int SBASE(int l)    { return (l == 0) ? 0 : (l == 1) ? 50 : (l == 2) ? 63 : 67; }
__device__ __forceinline__ int LBASE(int l)    { return (l == 0) ? 0 : (l == 1) ? 6400 : (l == 2) ? 8000 : 8400; }
__device__ __forceinline__ int NSQ(int l)      { return (l == 0) ? 6400 : (l == 1) ? 1600 : (l == 2) ? 400 : 100; }
__device__ __forceinline__ int NLV(int l)      { return (l == 0) ? 80 : (l == 1) ? 40 : (l == 2) ? 20 : 10; }
__device__ __forceinline__ float SFV(int l)    { return (l == 0) ? 8.f : (l == 1) ? 16.f : (l == 2) ? 32.f : 64.f; }

__device__ __forceinline__ float clampp(float p) {
    return fminf(fmaxf(p, 1e-7f), 1.0f - 1e-7f);
}

// monotone float -> uint32 (total order matching float <)
__device__ __forceinline__ unsigned f2mono(float f) {
    unsigned u = __float_as_uint(f);
    return (u & 0x80000000u) ? ~u : (u | 0x80000000u);
}

__device__ __forceinline__ float pair_iou(float4 d, float g0, float g1, float g2, float g3) {
    float tlx = fmaxf(d.x, g0), tly = fmaxf(d.y, g1);
    float brx = fminf(d.z, g2), bry = fminf(d.w, g3);
    float wx = fmaxf(brx - tlx, 0.f), wy = fmaxf(bry - tly, 0.f);
    float inter = wx * wy;
    float aa  = (d.z - d.x) * (d.w - d.y);
    float ab2 = (g2 - g0) * (g3 - g1);
    return inter / (aa + ab2 - inter + 1e-16f);
}

// precise cost (used only in rare k3 sentinel fallback)
__device__ __forceinline__ float pair_cost(float ns, float p, float iou) {
    float cls = ns + log1pf(-p) - logf(p);
    return cls + 3.f * (-logf(iou + 1e-8f));
}
// fast cost for selection (ranking-only; gaps >> 1e-6 perturbation)
__device__ __forceinline__ float pair_cost_fast(float ns, float p, float iou) {
    return ns + __logf(__fdividef(1.0f - p, p)) - 3.f * __logf(iou + 1e-8f);
}

// ---------------- kernel 1: per-prior prep (warp per prior; masked dec fused) ----------------
__global__ void __launch_bounds__(256) k1_prep(
    const float4* __restrict__ priors,
    const float*  __restrict__ clsp,
    const float4* __restrict__ gtb,
    const float4* __restrict__ dec)
{
    if (blockIdx.x == 0 && threadIdx.x < 5) g_acc[threadIdx.x] = 0.0;

    int w    = (blockIdx.x * blockDim.x + threadIdx.x) >> 5;
    int lane = threadIdx.x & 31;
    if (w >= BB * NN) return;
    int b = w / NN, i = w - b * NN;

    // 80 classes = 20 float4; lanes 0..19 each take one
    float a_ns = 0.f, a_bg = 0.f;
    if (lane < 20) {
        const float4* cp4 = (const float4*)(clsp + (size_t)w * CC);
        float4 v = cp4[lane];
        float l0 = __log2f(1.0f - v.x);
        float l1 = __log2f(1.0f - v.y);
        float l2 = __log2f(1.0f - v.z);
        float l3 = __log2f(1.0f - v.w);
        a_ns = ((l0 + l1) + (l2 + l3));
        a_bg = l0 * v.x * v.x + l1 * v.y * v.y + l2 * v.z * v.z + l3 * v.w * v.w;
    }
#pragma unroll
    for (int off = 16; off; off >>= 1) {
        a_ns += __shfl_down_sync(0xffffffffu, a_ns, off);
        a_bg += __shfl_down_sync(0xffffffffu, a_bg, off);
    }

    float4 pr = priors[i];
    float cx = pr.x, cy = pr.y, s = pr.z;
    const float4* gb = gtb + (size_t)b * GG;
    bool any = false;
#pragma unroll
    for (int g = lane; g < GG; g += 32) {
        float4 gq = gb[g];
        float ibv = fminf(fminf(cx - gq.x, cy - gq.y), fminf(gq.z - cx, gq.w - cy));
        float gcx = (gq.x + gq.z) * 0.5f, gcy = (gq.y + gq.w) * 0.5f;
        float r = 2.5f * s;
        float icv = fminf(fminf(cx - gcx + r, cy - gcy + r), fminf(gcx + r - cx, gcy + r - cy));
        any = any || (ibv > 0.f) || (icv > 0.f);
    }
    unsigned bal = __ballot_sync(0xffffffffu, any);
    if (lane == 0) {
        g_neg_sum[w] = -0.69314718f * a_ns;            // ln2
        g_bg_vfl[w]  = -0.75f * 0.69314718f * a_bg;
        g_valid[w]   = bal ? 1 : 0;
        float4 d = dec[w];
        if (!bal) d = make_float4(-1e30f, -1e30f, -1e30f, -1e30f);
        g_mdec[w] = d;
    }
    if (lane < 4) g_match[(size_t)w * 4 + lane] = 0u;
    if (lane == 4) g_best[w] = 0xFFFFFFFFFFFFFFFFull;
}

// ---------------- kernel 1c: per-strip AABB of valid decoded boxes ----------------
__global__ void __launch_bounds__(256) k1c_aabb()
{
    int w    = (blockIdx.x * blockDim.x + threadIdx.x) >> 5;
    int lane = threadIdx.x & 31;
    if (w >= BB * NSTRIP) return;
    int b = w / NSTRIP, s = w - b * NSTRIP;
    int l = lvl_of(s);
    int o = (s - SBASE(l)) * 128;
    int start = LBASE(l) + o;
    int sz = NSQ(l) - o; if (sz > 128) sz = 128;

    float mnx = 1e30f, mny = 1e30f, mxx = -1e30f, mxy = -1e30f;
    const float4* md = g_mdec + (size_t)b * NN;
    for (int j = lane; j < sz; j += 32) {
        float4 d = md[start + j];
        if (d.x > -1e29f) {          // exclude invalid-sentinel boxes
            mnx = fminf(mnx, d.x); mny = fminf(mny, d.y);
            mxx = fmaxf(mxx, d.z); mxy = fmaxf(mxy, d.w);
        }
    }
#pragma unroll
    for (int off = 16; off; off >>= 1) {
        mnx = fminf(mnx, __shfl_down_sync(0xffffffffu, mnx, off));
        mny = fminf(mny, __shfl_down_sync(0xffffffffu, mny, off));
        mxx = fmaxf(mxx, __shfl_down_sync(0xffffffffu, mxx, off));
        mxy = fmaxf(mxy, __shfl_down_sync(0xffffffffu, mxy, off));
    }
    if (lane == 0) g_aabb[b * NSTRIP + s] = make_float4(mnx, mny, mxx, mxy);
}

// exact integer bounds: smallest ix in [0,n] with (ix+0.5f)*s > L (n => empty)
__device__ __forceinline__ int lo_bnd(float L, float sf, int n) {
    int c = (int)floorf(__fdividef(L, sf)) - 1;
    if (c < 0) c = 0;
    while (c < n && !(((float)c + 0.5f) * sf > L)) c++;
    return c;
}
// largest ix in [-1,n-1] with (ix+0.5f)*s < H (-1 => empty)
__device__ __forceinline__ int hi_bnd(float H, float sf, int n) {
    int c = (int)floorf(__fdividef(H, sf)) + 1;
    if (c > n - 1) c = n - 1;
    while (c >= 0 && !(((float)c + 0.5f) * sf < H)) c--;
    return c;
}

union SmemU {
    float              f[TPB2 * 10];
    unsigned long long k[TPB2 * 10];
};

// ---------------- kernel 2: SimOTA assignment, one block per (b,g) column ----------------
__global__ void __launch_bounds__(TPB2, 5) k2_assign(
    const float4* __restrict__ priors,
    const float4* __restrict__ dec,
    const float*  __restrict__ clsp,
    const float4* __restrict__ gtb,
    const int*    __restrict__ gtl)
{
    const int g = blockIdx.x, b = blockIdx.y;
    const int tid = threadIdx.x;

    float4 gq = gtb[(size_t)b * GG + g];
    const float g0 = gq.x, g1 = gq.y, g2 = gq.z, g3 = gq.w;
    const float gcx = (g0 + g2) * 0.5f, gcy = (g1 + g3) * 0.5f;
    const float ab2 = (g2 - g0) * (g3 - g1);
    const int   lbl = gtl[b * GG + g];
    const float4* md  = g_mdec + (size_t)b * NN;
    const float*  cb  = clsp + (size_t)b * NN * CC;
    const float*  nsb = g_neg_sum + (size_t)b * NN;
    unsigned long long* bestb = g_best + (size_t)b * NN;

    __shared__ SmemU sh;
    __shared__ int s_lvl[4][6];     // xlo,xhi,ylo,yhi,clo,chi per level
    __shared__ int s_list[NSTRIP + 4];
    __shared__ int s_nlist, s_cnt, s_dynk;

    if (tid == 0) { s_nlist = 0; s_cnt = 0; }
    if (tid < 4) {
        float sf = SFV(tid);
        int   nn = NLV(tid);
        float Lx = fmaxf(g0, gcx - 2.5f * sf), Hx = fminf(g2, gcx + 2.5f * sf);
        float Ly = fmaxf(g1, gcy - 2.5f * sf), Hy = fminf(g3, gcy + 2.5f * sf);
        int xlo = lo_bnd(Lx, sf, nn), xhi = hi_bnd(Hx, sf, nn);
        int ylo = lo_bnd(Ly, sf, nn), yhi = hi_bnd(Hy, sf, nn);
        s_lvl[tid][0] = xlo; s_lvl[tid][1] = xhi;
        s_lvl[tid][2] = ylo; s_lvl[tid][3] = yhi;
        s_lvl[tid][4] = ylo * nn + xlo;  // cost-candidate min level-index
        s_lvl[tid][5] = yhi * nn + xhi;  // cost-candidate max level-index
    }
    __syncthreads();

    // build compact list of strips that can contribute (order irrelevant: sets are order-free)
    if (tid < NSTRIP) {
        int s = tid;
        int l = lvl_of(s);
        int o = (s - SBASE(l)) * 128;
        int sz = NSQ(l) - o; if (sz > 128) sz = 128;
        float4 ab = g_aabb[b * NSTRIP + s];
        bool niou = (ab.z > g0) && (ab.x < g2) && (ab.w > g1) && (ab.y < g3);
        bool rectok = (s_lvl[l][0] <= s_lvl[l][1]) && (s_lvl[l][2] <= s_lvl[l][3]);
        bool ncost = rectok && (o <= s_lvl[l][5]) && (o + sz - 1 >= s_lvl[l][4]);
        if (niou || ncost) {
            int pos = atomicAdd(&s_nlist, 1);
            s_list[pos] = s | (niou ? 0x100 : 0);
        }
    }
    __syncthreads();
    const int nlist = s_nlist;

    float tiou[10];
    unsigned long long tkey[10];
#pragma unroll
    for (int j = 0; j < 10; j++) { tiou[j] = 0.f; tkey[j] = 0xFFFFFFFFFFFFFFFFull; }
    int cnt = 0;

    for (int j = 0; j < nlist; j++) {
        int e = s_list[j];
        int s = e & 0xFF;
        bool niou = (e & 0x100) != 0;
        int l = lvl_of(s);
        int o = (s - SBASE(l)) * 128;
        int base = LBASE(l) + o;
        int sz = NSQ(l) - o; if (sz > 128) sz = 128;
        bool inr = tid < sz;

        // prefetch next listed strip into L1 (clamped to stay in-array)
        if (j + 1 < nlist) {
            int s2 = s_list[j + 1] & 0xFF;
            int l2 = lvl_of(s2);
            int b2 = LBASE(l2) + (s2 - SBASE(l2)) * 128;
            int pi = (b2 + tid < NN) ? (b2 + tid) : b2;
            asm volatile("prefetch.global.L1 [%0];" :: "l"(md + pi));
        }

        float iou = 0.f;
        if (niou && inr) {
            float4 d = md[base + tid];
            float wy = fminf(d.w, g3) - fmaxf(d.y, g1);
            float wx = fminf(d.z, g2) - fmaxf(d.x, g0);
            if (fminf(wx, wy) > 0.f) {
                float inter = wx * wy;
                float aa = (d.z - d.x) * (d.w - d.y);
                iou = __fdividef(inter, aa + ab2 - inter + 1e-16f);
                if (iou > tiou[9]) {
                    tiou[9] = iou;
#pragma unroll
                    for (int q = 9; q > 0; q--)
                        if (tiou[q] > tiou[q - 1]) { float tt = tiou[q]; tiou[q] = tiou[q - 1]; tiou[q - 1] = tt; }
                }
            }
        }
        if (inr) {
            int myi = o + tid;
            int iy, ix;
            if (l == 0)      { iy = myi / 80; ix = myi - iy * 80; }
            else if (l == 1) { iy = myi / 40; ix = myi - iy * 40; }
            else if (l == 2) { iy = myi / 20; ix = myi - iy * 20; }
            else             { iy = myi / 10; ix = myi - iy * 10; }
            if (ix >= s_lvl[l][0] && ix <= s_lvl[l][1] && iy >= s_lvl[l][2] && iy <= s_lvl[l][3]) {
                // in_both (boundary-exact) => valid; cost < 1e5 so always outranks penalized
                cnt++;
                int gi = base + tid;
                float p = clampp(cb[(size_t)gi * CC + lbl]);
                float cost = pair_cost_fast(nsb[gi], p, iou);
                unsigned mono = f2mono(cost);
                unsigned long long key = ((unsigned long long)mono << 32) | (unsigned)gi;
                if (key < tkey[9]) {
                    tkey[9] = key;
#pragma unroll
                    for (int q = 9; q > 0; q--)
                        if (tkey[q] < tkey[q - 1]) { unsigned long long tt = tkey[q]; tkey[q] = tkey[q - 1]; tkey[q - 1] = tt; }
                }
                // record per-prior argmin over g (ties -> lowest g, matching jnp.argmin)
                atomicMin(&bestb[gi], ((unsigned long long)mono << 32) | (unsigned)g);
            }
        }
    }

    atomicAdd(&s_cnt, cnt);
#pragma unroll
    for (int j = 0; j < 10; j++) sh.f[tid * 10 + j] = tiou[j];
    __syncthreads();

    // tree-merge top-10 IoUs (descending)
    for (int str = TPB2 >> 1; str >= 1; str >>= 1) {
        if (tid < str) {
            float* A  = &sh.f[tid * 10];
            float* Bp = &sh.f[(tid + str) * 10];
            float tmp[10]; int ia = 0, ib2 = 0;
#pragma unroll
            for (int t2 = 0; t2 < 10; t2++) {
                if (A[ia] >= Bp[ib2]) tmp[t2] = A[ia++]; else tmp[t2] = Bp[ib2++];
            }
#pragma unroll
            for (int t2 = 0; t2 < 10; t2++) A[t2] = tmp[t2];
        }
        __syncthreads();
    }
    if (tid == 0) {
        float sum = 0.f;
#pragma unroll
        for (int j = 0; j < 10; j++) sum += sh.f[j];
        int dynk = (int)sum;
        if (dynk < 1)  dynk = 1;
        if (dynk > 10) dynk = 10;
        s_dynk = dynk;
    }
    __syncthreads();   // protect sh.f reads before key phase reuses the union

    int nib = s_cnt;
    if (nib < 10) {
        // exact fallback: full column with penalty terms (columns with <10 in_both priors)
        const unsigned char* vb = g_valid + (size_t)b * NN;
        const float4* db = dec + (size_t)b * NN;
#pragma unroll
        for (int j = 0; j < 10; j++) tkey[j] = 0xFFFFFFFFFFFFFFFFull;
        for (int i = tid; i < NN; i += TPB2) {
            float4 pr = priors[i];
            float cx = pr.x, cy = pr.y, s = pr.z;
            float ibv = fminf(fminf(cx - g0, cy - g1), fminf(g2 - cx, g3 - cy));
            float r = 2.5f * s;
            float icv = fminf(fminf(cx - gcx + r, cy - gcy + r), fminf(gcx + r - cx, gcy + r - cy));
            bool in_both = (ibv > 0.f) && (icv > 0.f);
            float4 d = db[i];
            float iou = pair_iou(d, g0, g1, g2, g3);
            bool val = vb[i] != 0;
            float p = clampp(cb[(size_t)i * CC + lbl]);
            float cost = pair_cost_fast(nsb[i], p, iou);
            if (!in_both) cost += 100000.0f;
            if (!val)     cost += 100000000.0f;
            unsigned long long key = ((unsigned long long)f2mono(cost) << 32) | (unsigned)i;
            if (key < tkey[9]) {
                tkey[9] = key;
#pragma unroll
                for (int q = 9; q > 0; q--)
                    if (tkey[q] < tkey[q - 1]) { unsigned long long tt = tkey[q]; tkey[q] = tkey[q - 1]; tkey[q - 1] = tt; }
            }
        }
    }

#pragma unroll
    for (int j = 0; j < 10; j++) sh.k[tid * 10 + j] = tkey[j];
    __syncthreads();
    // tree-merge cost keys (ascending; index in low bits => stable ties)
    for (int str = TPB2 >> 1; str >= 1; str >>= 1) {
        if (tid < str) {
            unsigned long long* A  = &sh.k[tid * 10];
            unsigned long long* Bp = &sh.k[(tid + str) * 10];
            unsigned long long tmp[10]; int ia = 0, ib2 = 0;
#pragma unroll
            for (int t2 = 0; t2 < 10; t2++) {
                if (A[ia] <= Bp[ib2]) tmp[t2] = A[ia++]; else tmp[t2] = Bp[ib2++];
            }
#pragma unroll
            for (int t2 = 0; t2 < 10; t2++) A[t2] = tmp[t2];
        }
        __syncthreads();
    }

    if (tid == 0) {
        int dynk = s_dynk;
        unsigned bit = 1u << (g & 31);
        int word = g >> 5;
        for (int j = 0; j < dynk; j++) {
            unsigned long long k = sh.k[j];
            if (k == 0xFFFFFFFFFFFFFFFFull) break;
            int i = (int)(k & 0xFFFFFFFFu);
            atomicOr(&g_match[((size_t)b * NN + i) * 4 + word], bit);
        }
    }
}

// ---------------- kernel 3: per-prior loss terms ----------------
__global__ void __launch_bounds__(256) k3_loss(
    const float4* __restrict__ priors,
    const float4* __restrict__ dec,
    const float*  __restrict__ clsp,
    const float*  __restrict__ regp,
    const float4* __restrict__ gtb,
    const int*    __restrict__ gtl)
{
    int idx = blockIdx.x * blockDim.x + threadIdx.x;
    int tid = threadIdx.x;
    float v_vfl = 0.f, v_gi = 0.f, v_df = 0.f, v_fg = 0.f, v_ts = 0.f;

    if (idx < BB * NN) {
        int b = idx / NN, i = idx - b * NN;
        uint4 mw = *((const uint4*)&g_match[(size_t)idx * 4]);
        unsigned m0 = mw.x, m1 = mw.y, m2 = mw.z, m3 = mw.w;
        int nm = __popc(m0) + __popc(m1) + __popc(m2) + __popc(m3);

        const float4* gb = gtb + (size_t)b * GG;
        float4 d = dec[idx];
        int mgt = 0;
        float mious = 0.f;

        if (nm == 1) {
            mgt = m0 ? (__ffs(m0) - 1)
                     : (m1 ? (31 + __ffs(m1))
                           : (m2 ? (63 + __ffs(m2)) : (95 + __ffs(m3))));
            float4 q = gb[mgt];
            mious = pair_iou(d, q.x, q.y, q.z, q.w);
        } else if (nm > 1) {
            // multi-match: argmin_g cost recorded by k2 over in_both columns
            unsigned long long bst = g_best[idx];
            if (bst != 0xFFFFFFFFFFFFFFFFull) {
                mgt = (int)(bst & 0xFFFFFFFFu);
            } else {
                // sentinel: matched only via penalized fallback selections; full argmin
                float4 pr = priors[i];
                float cx = pr.x, cy = pr.y, s = pr.z;
                bool val = g_valid[idx] != 0;
                float ns = g_neg_sum[idx];
                const float* cp = clsp + (size_t)idx * CC;
                const int* gl = gtl + b * GG;
                float best = 3.4e38f; int bestg = 0;
                for (int g = 0; g < GG; g++) {
                    float4 q = gb[g];
                    float ibv = fminf(fminf(cx - q.x, cy - q.y), fminf(q.z - cx, q.w - cy));
                    float gcx = (q.x + q.z) * 0.5f, gcy = (q.y + q.w) * 0.5f;
                    float r = 2.5f * s;
                    float icv = fminf(fminf(cx - gcx + r, cy - gcy + r), fminf(gcx + r - cx, gcy + r - cy));
                    bool ib2 = (ibv > 0.f) && (icv > 0.f);
                    float iou = pair_iou(d, q.x, q.y, q.z, q.w);
                    float p = clampp(cp[gl[g]]);
                    float cost = pair_cost(ns, p, iou);
                    if (!ib2) cost += 100000.0f;
                    if (!val) cost += 100000000.0f;
                    if (cost < best) { best = cost; bestg = g; }
                }
                mgt = bestg;
            }
            float4 q = gb[mgt];
            mious = pair_iou(d, q.x, q.y, q.z, q.w);
        }

        bool fg = nm > 0;
        float tscore = fg ? mious : 0.f;
        v_vfl = g_bg_vfl[idx];   // background VFL for all classes
        v_fg  = fg ? 1.f : 0.f;
        v_ts  = tscore;

        if (tscore > 0.f) {
            // VFL correction at matched label
            int lbl = gtl[b * GG + mgt];
            float p = clampp(clsp[(size_t)idx * CC + lbl]);
            float l1p = log1pf(-p);
            float t = tscore;
            float bce = -(t * logf(p) + (1.f - t) * l1p);
            v_vfl += bce * t - (-l1p * 0.75f * p * p);

            float4 q = gb[mgt];
            // GIoU loss
            {
                float tlx = fmaxf(d.x, q.x), tly = fmaxf(d.y, q.y);
                float brx = fminf(d.z, q.z), bry = fminf(d.w, q.w);
                float wx = fmaxf(brx - tlx, 0.f), wy = fmaxf(bry - tly, 0.f);
                float inter = wx * wy;
                float ap = fmaxf(d.z - d.x, 0.f) * fmaxf(d.w - d.y, 0.f);
                float at = fmaxf(q.z - q.x, 0.f) * fmaxf(q.w - q.y, 0.f);
                float un = ap + at - inter;
                float iou2 = inter / (un + 1e-16f);
                float c0 = fminf(d.x, q.x), c1 = fminf(d.y, q.y);
                float c2 = fmaxf(d.z, q.z), c3 = fmaxf(d.w, q.w);
                float cw = fmaxf(c2 - c0, 0.f), ch = fmaxf(c3 - c1, 0.f);
                float ac = cw * ch;
                v_gi = (1.f - (iou2 - (ac - un) / (ac + 1e-16f))) * t;
            }
            // DFL
            {
                float4 pr = priors[i];
                float cx = pr.x, cy = pr.y, s = pr.z;
                float ddv[4] = { (cx - q.x) / s, (cy - q.y) / s, (q.z - cx) / s, (q.w - cy) / s };
                const float* rp = regp + (size_t)idx * 32;
                float cesum = 0.f;
#pragma unroll
                for (int e = 0; e < 4; e++) {
                    float x[8];
#pragma unroll
                    for (int j = 0; j < 8; j++) x[j] = rp[e * 8 + j];
                    float mx = x[0];
#pragma unroll
                    for (int j = 1; j < 8; j++) mx = fmaxf(mx, x[j]);
                    float se = 0.f;
#pragma unroll
                    for (int j = 0; j < 8; j++) se += expf(x[j] - mx);
                    float lse = mx + logf(se);
                    float tt = fminf(fmaxf(ddv[e], 0.f), 6.9f);
                    int tl_ = (int)tt;
                    int tr_ = tl_ + 1 < 7 ? tl_ + 1 : 7;
                    float wl = (float)(tl_ + 1) - tt;
                    float wr = tt - (float)tl_;
                    cesum += -((x[tl_] - lse) * wl + (x[tr_] - lse) * wr);
                }
                v_df = cesum * t;
            }
        }
    }

    // reduce 5 accumulators: warp shuffle + one sync + warp 0 finish
    float vals[5] = { v_vfl, v_gi, v_df, v_fg, v_ts };
    int lane = tid & 31, wid = tid >> 5;
    __shared__ float swr[8][5];
#pragma unroll
    for (int k = 0; k < 5; k++) {
        float v = vals[k];
#pragma unroll
        for (int off = 16; off; off >>= 1) v += __shfl_down_sync(0xffffffffu, v, off);
        if (lane == 0) swr[wid][k] = v;
    }
    __syncthreads();
    if (wid == 0) {
#pragma unroll
        for (int k = 0; k < 5; k++) {
            float v = (lane < 8) ? swr[lane][k] : 0.f;
#pragma unroll
            for (int off = 4; off; off >>= 1) v += __shfl_down_sync(0xffffffffu, v, off);
            if (lane == 0) atomicAdd(&g_acc[k], (double)v);
        }
    }
}

// ---------------- kernel 4: final combine ----------------
__global__ void k4_final(float* out) {
    double npos = g_acc[3] > 1.0 ? g_acc[3] : 1.0;
    double nsc  = g_acc[4] > 1.0 ? g_acc[4] : 1.0;
    out[0] = (float)(g_acc[0] / npos + 2.0 * g_acc[1] / nsc + 0.25 * g_acc[2] / nsc);
}

extern "C" void kernel_launch(void* const* d_in, const int* in_sizes, int n_in,
                              void* d_out, int out_size)
{
    const float4* priors = (const float4*)d_in[0];
    const float4* dec    = (const float4*)d_in[1];
    const float*  clsp   = (const float*)d_in[2];
    const float*  regp   = (const float*)d_in[3];
    const float4* gtb    = (const float4*)d_in[4];
    const int*    gtl    = (const int*)d_in[5];

    k1_prep<<<(BB * NN) / 8, 256>>>(priors, clsp, gtb, dec);
    k1c_aabb<<<(BB * NSTRIP * 32 + 255) / 256, 256>>>();
    dim3 g2(GG, BB);
    k2_assign<<<g2, TPB2>>>(priors, dec, clsp, gtb, gtl);
    k3_loss<<<(BB * NN + 255) / 256, 256>>>(priors, dec, clsp, regp, gtb, gtl);
    k4_final<<<1, 1>>>((float*)d_out);
}